// round 1
// baseline (speedup 1.0000x reference)
#include <cuda_runtime.h>
#include <math.h>
#include <limits.h>

#define BB 16384
#define DD 1024
#define E3 3072
#define NG 64

// ---------------- scratch (device globals; no allocations allowed) ----------
__device__ float g_Y[(size_t)BB * E3];     // x_s @ intra_in_w^T   [16384,3072]
__device__ float g_om[(size_t)BB * DD];    // o_mean               [16384,1024]
__device__ int   g_perm[BB];
__device__ int   g_ls[BB];
__device__ int   g_counts[NG];
__device__ int   g_gstart[NG + 1];
__device__ int   g_first[NG];
__device__ float g_c2[E3];
__device__ float g_c4[E3];
__device__ float g_cb[DD];
__device__ float g_M[DD * DD];             // lin_w @ intra_out_w
__device__ float g_u[NG * DD];
__device__ float g_f[NG * DD];
__device__ float g_colsum[DD];
__device__ float g_imean[NG * DD];
__device__ float g_iscale[1];

// ---------------- small setup kernels ---------------------------------------
__global__ void k_init() {
    int t = threadIdx.x;
    if (t < NG) { g_counts[t] = 0; g_first[t] = INT_MAX; }
}

__global__ void k_hist(const int* __restrict__ labels) {
    int i = blockIdx.x * blockDim.x + threadIdx.x;
    if (i < BB) {
        int g = labels[i];
        atomicAdd(&g_counts[g], 1);
        atomicMin(&g_first[g], i);
    }
}

__global__ void k_prefix() {
    int s = 0, np = 0;
    for (int g = 0; g < NG; ++g) {
        g_gstart[g] = s;
        s += g_counts[g];
        if (g_counts[g] > 0) np++;
    }
    g_gstart[NG] = s;
    g_iscale[0] = (np > 1) ? 1.0f / (float)(np - 1) : 0.0f;
}

// Stable counting sort: block g writes positions of all i with labels[i]==g,
// preserving original order (matches stable jnp.argsort).
__global__ void k_perm(const int* __restrict__ labels) {
    __shared__ int sflags[256];
    int g = blockIdx.x;
    int tid = threadIdx.x;
    int base = g_gstart[g];
    int running = 0;
    for (int c0 = 0; c0 < BB; c0 += 256) {
        int i = c0 + tid;
        int flag = (labels[i] == g) ? 1 : 0;
        __syncthreads();
        sflags[tid] = flag;
        __syncthreads();
        for (int off = 1; off < 256; off <<= 1) {
            int v = (tid >= off) ? sflags[tid - off] : 0;
            __syncthreads();
            sflags[tid] += v;
            __syncthreads();
        }
        if (flag) {
            int pos = base + running + sflags[tid] - 1;
            g_perm[pos] = i;
            g_ls[pos] = g;
        }
        running += sflags[255];
    }
}

// c2/c4: qkv bias terms: conv_b * rowsum(W) + in_b
__global__ void k_cvec(const float* __restrict__ iiw, const float* __restrict__ iib,
                       const float* __restrict__ cb2, const float* __restrict__ cb4) {
    int e = blockIdx.x * blockDim.x + threadIdx.x;
    if (e < E3) {
        const float* w = iiw + (size_t)e * DD;
        float rs = 0.f;
        #pragma unroll 4
        for (int d = 0; d < DD; ++d) rs += w[d];
        g_c2[e] = cb2[0] * rs + iib[e];
        g_c4[e] = cb4[0] * rs + iib[e];
    }
}

// cb: lin_b + lin_w @ intra_out_b
__global__ void k_cb(const float* __restrict__ lw, const float* __restrict__ iob,
                     const float* __restrict__ lb) {
    int e = blockIdx.x * blockDim.x + threadIdx.x;
    if (e < DD) {
        const float* w = lw + (size_t)e * DD;
        float s = lb[e];
        #pragma unroll 4
        for (int d = 0; d < DD; ++d) s += w[d] * iob[d];
        g_cb[e] = s;
    }
}

// ---------------- GEMM: Y = x[perm] @ intra_in_w^T  [16384,3072] ------------
__global__ __launch_bounds__(256) void gemm_y(const float* __restrict__ x,
                                              const float* __restrict__ W) {
    __shared__ float As[8][128];
    __shared__ float Bs[8][128];
    __shared__ int sperm[128];
    int tid = threadIdx.x;
    int mBase = blockIdx.y * 128;
    int nBase = blockIdx.x * 128;
    if (tid < 128) sperm[tid] = g_perm[mBase + tid];
    __syncthreads();
    int lr = tid >> 1;
    int lc = (tid & 1) << 2;
    const float* aPtr = x + (size_t)sperm[lr] * DD + lc;
    const float* bPtr = W + (size_t)(nBase + lr) * DD + lc;
    int ty = tid >> 4, tx = tid & 15;
    float acc[8][8];
    #pragma unroll
    for (int i = 0; i < 8; i++)
        #pragma unroll
        for (int j = 0; j < 8; j++) acc[i][j] = 0.f;
    for (int k0 = 0; k0 < DD; k0 += 8) {
        float4 a4 = *(const float4*)(aPtr + k0);
        float4 b4 = *(const float4*)(bPtr + k0);
        As[lc + 0][lr] = a4.x; As[lc + 1][lr] = a4.y; As[lc + 2][lr] = a4.z; As[lc + 3][lr] = a4.w;
        Bs[lc + 0][lr] = b4.x; Bs[lc + 1][lr] = b4.y; Bs[lc + 2][lr] = b4.z; Bs[lc + 3][lr] = b4.w;
        __syncthreads();
        #pragma unroll
        for (int k = 0; k < 8; ++k) {
            float4 ra0 = *(const float4*)&As[k][ty * 8];
            float4 ra1 = *(const float4*)&As[k][ty * 8 + 4];
            float4 rb0 = *(const float4*)&Bs[k][tx * 8];
            float4 rb1 = *(const float4*)&Bs[k][tx * 8 + 4];
            float ra[8] = {ra0.x, ra0.y, ra0.z, ra0.w, ra1.x, ra1.y, ra1.z, ra1.w};
            float rb[8] = {rb0.x, rb0.y, rb0.z, rb0.w, rb1.x, rb1.y, rb1.z, rb1.w};
            #pragma unroll
            for (int i = 0; i < 8; i++)
                #pragma unroll
                for (int j = 0; j < 8; j++) acc[i][j] += ra[i] * rb[j];
        }
        __syncthreads();
    }
    #pragma unroll
    for (int i = 0; i < 8; i++) {
        float* cp = g_Y + (size_t)(mBase + ty * 8 + i) * E3 + nBase + tx * 8;
        float4 v0 = {acc[i][0], acc[i][1], acc[i][2], acc[i][3]};
        float4 v1 = {acc[i][4], acc[i][5], acc[i][6], acc[i][7]};
        *(float4*)cp = v0;
        *((float4*)cp + 1) = v1;
    }
}

// ---------------- fused conv + S=2 attention + mean -------------------------
__global__ __launch_bounds__(256) void k_attn(const float* __restrict__ cw2,
                                              const float* __restrict__ cw4) {
    __shared__ float s2[E3];
    __shared__ float s4[E3];
    __shared__ float red[8][8];
    __shared__ float sw[2][2];
    int i = blockIdx.x;
    int tid = threadIdx.x;
    int g = g_ls[i];
    int gs = g_gstart[g];
    int ge = g_gstart[g + 1];
    bool mm1 = (i - 1 >= gs);
    bool mm2 = (i - 2 >= gs);
    bool mp1 = (i + 1 < ge);
    float w20 = cw2[0], w21 = cw2[1];
    float w40 = cw4[0], w41 = cw4[1], w42 = cw4[2], w43 = cw4[3];
    const float* Y0 = g_Y + (size_t)i * E3;
    const float* Ym1 = g_Y + (size_t)(i - 1) * E3;
    const float* Ym2 = g_Y + (size_t)(i - 2) * E3;
    const float* Yp1 = g_Y + (size_t)(i + 1) * E3;
    for (int e = tid; e < E3; e += 256) {
        float y0 = Y0[e];
        float ym1 = mm1 ? Ym1[e] : 0.f;
        float ym2 = mm2 ? Ym2[e] : 0.f;
        float yp1 = mp1 ? Yp1[e] : 0.f;
        s2[e] = w20 * ym1 + w21 * y0 + g_c2[e];
        s4[e] = w40 * ym2 + w41 * ym1 + w42 * y0 + w43 * yp1 + g_c4[e];
    }
    __syncthreads();
    // 8 dots: acc[h*4 + s*2 + t] = q_s(h) . k_t(h), s,t in {t2,t4}
    float acc[8] = {0, 0, 0, 0, 0, 0, 0, 0};
    for (int d = tid; d < 512; d += 256) {
        #pragma unroll
        for (int h = 0; h < 2; ++h) {
            float q2 = s2[h * 512 + d];
            float q4 = s4[h * 512 + d];
            float k2 = s2[1024 + h * 512 + d];
            float k4 = s4[1024 + h * 512 + d];
            acc[h * 4 + 0] += q2 * k2;
            acc[h * 4 + 1] += q2 * k4;
            acc[h * 4 + 2] += q4 * k2;
            acc[h * 4 + 3] += q4 * k4;
        }
    }
    int lane = tid & 31, warp = tid >> 5;
    #pragma unroll
    for (int a = 0; a < 8; ++a) {
        #pragma unroll
        for (int off = 16; off > 0; off >>= 1)
            acc[a] += __shfl_xor_sync(0xFFFFFFFFu, acc[a], off);
        if (lane == 0) red[a][warp] = acc[a];
    }
    __syncthreads();
    if (tid == 0) {
        const float scale = 0.04419417382415922f;  // 1/sqrt(512)
        #pragma unroll
        for (int h = 0; h < 2; ++h) {
            float sc[4];
            #pragma unroll
            for (int a = 0; a < 4; ++a) {
                float s = 0.f;
                #pragma unroll
                for (int w = 0; w < 8; ++w) s += red[h * 4 + a][w];
                sc[a] = s * scale;
            }
            // row q=0: (sc[0], sc[1]); row q=1: (sc[2], sc[3])
            float m0 = fmaxf(sc[0], sc[1]);
            float e00 = expf(sc[0] - m0), e01 = expf(sc[1] - m0);
            float r0 = 1.f / (e00 + e01);
            float m1 = fmaxf(sc[2], sc[3]);
            float e10 = expf(sc[2] - m1), e11 = expf(sc[3] - m1);
            float r1 = 1.f / (e10 + e11);
            sw[h][0] = 0.5f * (e00 * r0 + e10 * r1);
            sw[h][1] = 0.5f * (e01 * r0 + e11 * r1);
        }
    }
    __syncthreads();
    float* om = g_om + (size_t)i * DD;
    for (int e = tid; e < DD; e += 256) {
        int h = e >> 9;
        om[e] = sw[h][0] * s2[2048 + e] + sw[h][1] * s4[2048 + e];
    }
}

// ---------------- M = lin_w @ intra_out_w  (1024^3, NN) ---------------------
__global__ void gemm_nn_1024(const float* __restrict__ A, const float* __restrict__ Bm) {
    __shared__ float As[32][33], Bs[32][33];
    int tx = threadIdx.x, ty = threadIdx.y;
    int row = blockIdx.y * 32 + ty, col = blockIdx.x * 32 + tx;
    float acc = 0.f;
    for (int k0 = 0; k0 < DD; k0 += 32) {
        As[ty][tx] = A[(size_t)row * DD + k0 + tx];
        Bs[ty][tx] = Bm[(size_t)(k0 + ty) * DD + col];
        __syncthreads();
        #pragma unroll
        for (int k = 0; k < 32; ++k) acc += As[ty][k] * Bs[k][tx];
        __syncthreads();
    }
    g_M[(size_t)row * DD + col] = acc;
}

// ---------------- inter path (64 groups) ------------------------------------
__global__ void k_u(const float* __restrict__ x, const float* __restrict__ inw,
                    const float* __restrict__ inb) {
    int g = blockIdx.x;
    int e = blockIdx.y * 256 + threadIdx.x;
    if (g_counts[g] == 0) { g_u[g * DD + e] = 0.f; return; }
    const float* xr = x + (size_t)g_first[g] * DD;
    const float* wr = inw + (size_t)2 * DD * DD + (size_t)e * DD;  // Wv row e
    float s = inb[2 * DD + e];
    #pragma unroll 4
    for (int d = 0; d < DD; ++d) s += xr[d] * wr[d];
    g_u[g * DD + e] = s;
}

__global__ void k_f(const float* __restrict__ inow, const float* __restrict__ inob) {
    int g = blockIdx.x;
    int e = blockIdx.y * 256 + threadIdx.x;
    if (g_counts[g] == 0) { g_f[g * DD + e] = 0.f; return; }
    const float* ur = g_u + (size_t)g * DD;
    const float* wr = inow + (size_t)e * DD;
    float s = inob[e];
    #pragma unroll 4
    for (int d = 0; d < DD; ++d) s += ur[d] * wr[d];
    g_f[g * DD + e] = s;
}

__global__ void k_colsum() {
    int e = blockIdx.x * 256 + threadIdx.x;
    float s = 0.f;
    #pragma unroll
    for (int g = 0; g < NG; ++g) s += g_f[g * DD + e];
    g_colsum[e] = s;
}

__global__ void k_imean() {
    int g = blockIdx.x;
    float sc = g_iscale[0];
    for (int e = threadIdx.x; e < DD; e += 256)
        g_imean[g * DD + e] = (g_colsum[e] - g_f[g * DD + e]) * sc;
}

// ---------------- final GEMM: out[perm[i]] = om @ M^T + cb + imean[ls] ------
__global__ __launch_bounds__(256) void gemm_final(float* __restrict__ out) {
    __shared__ float As[8][128];
    __shared__ float Bs[8][128];
    __shared__ int sperm[128];
    __shared__ int sls[128];
    int tid = threadIdx.x;
    int mBase = blockIdx.y * 128;
    int nBase = blockIdx.x * 128;
    if (tid < 128) {
        sperm[tid] = g_perm[mBase + tid];
        sls[tid] = g_ls[mBase + tid];
    }
    __syncthreads();
    int lr = tid >> 1;
    int lc = (tid & 1) << 2;
    const float* aPtr = g_om + (size_t)(mBase + lr) * DD + lc;
    const float* bPtr = g_M + (size_t)(nBase + lr) * DD + lc;
    int ty = tid >> 4, tx = tid & 15;
    float acc[8][8];
    #pragma unroll
    for (int i = 0; i < 8; i++)
        #pragma unroll
        for (int j = 0; j < 8; j++) acc[i][j] = 0.f;
    for (int k0 = 0; k0 < DD; k0 += 8) {
        float4 a4 = *(const float4*)(aPtr + k0);
        float4 b4 = *(const float4*)(bPtr + k0);
        As[lc + 0][lr] = a4.x; As[lc + 1][lr] = a4.y; As[lc + 2][lr] = a4.z; As[lc + 3][lr] = a4.w;
        Bs[lc + 0][lr] = b4.x; Bs[lc + 1][lr] = b4.y; Bs[lc + 2][lr] = b4.z; Bs[lc + 3][lr] = b4.w;
        __syncthreads();
        #pragma unroll
        for (int k = 0; k < 8; ++k) {
            float4 ra0 = *(const float4*)&As[k][ty * 8];
            float4 ra1 = *(const float4*)&As[k][ty * 8 + 4];
            float4 rb0 = *(const float4*)&Bs[k][tx * 8];
            float4 rb1 = *(const float4*)&Bs[k][tx * 8 + 4];
            float ra[8] = {ra0.x, ra0.y, ra0.z, ra0.w, ra1.x, ra1.y, ra1.z, ra1.w};
            float rb[8] = {rb0.x, rb0.y, rb0.z, rb0.w, rb1.x, rb1.y, rb1.z, rb1.w};
            #pragma unroll
            for (int i = 0; i < 8; i++)
                #pragma unroll
                for (int j = 0; j < 8; j++) acc[i][j] += ra[i] * rb[j];
        }
        __syncthreads();
    }
    #pragma unroll
    for (int i = 0; i < 8; i++) {
        int srow = ty * 8 + i;
        int orow = sperm[srow];
        const float* im = g_imean + (size_t)sls[srow] * DD + nBase + tx * 8;
        const float* cbp = g_cb + nBase + tx * 8;
        float* cp = out + (size_t)orow * DD + nBase + tx * 8;
        float4 v0, v1;
        v0.x = acc[i][0] + cbp[0] + im[0];
        v0.y = acc[i][1] + cbp[1] + im[1];
        v0.z = acc[i][2] + cbp[2] + im[2];
        v0.w = acc[i][3] + cbp[3] + im[3];
        v1.x = acc[i][4] + cbp[4] + im[4];
        v1.y = acc[i][5] + cbp[5] + im[5];
        v1.z = acc[i][6] + cbp[6] + im[6];
        v1.w = acc[i][7] + cbp[7] + im[7];
        *(float4*)cp = v0;
        *((float4*)cp + 1) = v1;
    }
}

// ---------------- launch ------------------------------------------------------
extern "C" void kernel_launch(void* const* d_in, const int* in_sizes, int n_in,
                              void* d_out, int out_size) {
    const float* x = (const float*)d_in[0];
    const int* labels = (const int*)d_in[1];
    // num_groups may or may not be materialized as an input; detect via size.
    int o = (in_sizes[2] == 1) ? 1 : 0;
    const float* cw2 = (const float*)d_in[2 + o];
    const float* cb2 = (const float*)d_in[3 + o];
    const float* cw4 = (const float*)d_in[4 + o];
    const float* cb4 = (const float*)d_in[5 + o];
    const float* iiw = (const float*)d_in[6 + o];   // intra_in_w  [3072,1024]
    const float* iib = (const float*)d_in[7 + o];   // intra_in_b  [3072]
    const float* iow = (const float*)d_in[8 + o];   // intra_out_w [1024,1024]
    const float* iob = (const float*)d_in[9 + o];   // intra_out_b [1024]
    const float* inw = (const float*)d_in[10 + o];  // inter_in_w  [3072,1024]
    const float* inb = (const float*)d_in[11 + o];  // inter_in_b  [3072]
    const float* inow = (const float*)d_in[12 + o]; // inter_out_w [1024,1024]
    const float* inob = (const float*)d_in[13 + o]; // inter_out_b [1024]
    const float* lw = (const float*)d_in[14 + o];   // lin_w       [1024,1024]
    const float* lb = (const float*)d_in[15 + o];   // lin_b       [1024]
    float* out = (float*)d_out;

    k_init<<<1, 64>>>();
    k_hist<<<BB / 256, 256>>>(labels);
    k_prefix<<<1, 1>>>();
    k_perm<<<NG, 256>>>(labels);
    k_cvec<<<E3 / 256, 256>>>(iiw, iib, cb2, cb4);
    gemm_y<<<dim3(E3 / 128, BB / 128), 256>>>(x, iiw);
    k_attn<<<BB, 256>>>(cw2, cw4);
    k_cb<<<DD / 256, 256>>>(lw, iob, lb);
    gemm_nn_1024<<<dim3(32, 32), dim3(32, 32)>>>(lw, iow);
    k_u<<<dim3(NG, DD / 256), 256>>>(x, inw, inb);
    k_f<<<dim3(NG, DD / 256), 256>>>(inow, inob);
    k_colsum<<<DD / 256, 256>>>();
    k_imean<<<NG, 256>>>();
    gemm_final<<<dim3(DD / 128, BB / 128), 256>>>(out);
}